// round 1
// baseline (speedup 1.0000x reference)
#include <cuda_runtime.h>
#include <math.h>

// Problem constants
#define BB 16
#define LL 512
#define DD 128
#define HH 8
#define HB 128          // H*B
#define HD 1024         // H*D
#define MM 8192         // B*L
#define INV_SQRT_D 0.08838834764831843f

// Tiling
#define TS 128
#define KS 16
#define SPAD 132

// Scratch (device globals; allocation is forbidden)
__device__ float g_Q[HB * LL * DD];
__device__ float g_K[HB * LL * DD];
__device__ float g_V[HB * LL * DD];
__device__ float g_S[HB * LL * LL];     // scores -> attn (in place)
__device__ float g_ATT[HB * LL * DD];   // [H,B,L,D] contiguous == view(B,L,H*D)

// ---------------------------------------------------------------------------
// Shared helpers
// ---------------------------------------------------------------------------

// Load a TS x KS tile from a K-last (row-major, contraction on last dim)
// matrix, stored transposed into shared: Sm[kk][row].
__device__ __forceinline__ void load_tileT(float (*Sm)[SPAD], const float* __restrict__ src,
                                           int ldsrc, int row0, int k0, int tid) {
#pragma unroll
    for (int i = 0; i < (TS * KS) / 256; ++i) {
        int idx = tid + i * 256;
        int r = idx >> 4;     // 0..127
        int c = idx & 15;     // 0..15
        Sm[c][r] = src[(row0 + r) * ldsrc + (k0 + c)];
    }
}

// Load a KS x TS tile from a K-first matrix (rows = contraction dim),
// stored directly: Sm[kk][col].
__device__ __forceinline__ void load_tile_direct(float (*Sm)[SPAD], const float* __restrict__ src,
                                                 int ldsrc, int k0, int c0, int tid) {
#pragma unroll
    for (int i = 0; i < (KS * TS) / 256; ++i) {
        int idx = tid + i * 256;
        int kk = idx >> 7;    // 0..15
        int cc = idx & 127;   // 0..127
        Sm[kk][cc] = src[(k0 + kk) * ldsrc + (c0 + cc)];
    }
}

__device__ __forceinline__ void mma_tile(const float (*SA)[SPAD], const float (*SB)[SPAD],
                                         int ty, int tx, float acc[8][8]) {
#pragma unroll
    for (int kk = 0; kk < KS; ++kk) {
        float4 a0 = *(const float4*)&SA[kk][ty * 8];
        float4 a1 = *(const float4*)&SA[kk][ty * 8 + 4];
        float4 b0 = *(const float4*)&SB[kk][tx * 8];
        float4 b1 = *(const float4*)&SB[kk][tx * 8 + 4];
        float a[8] = {a0.x, a0.y, a0.z, a0.w, a1.x, a1.y, a1.z, a1.w};
        float b[8] = {b0.x, b0.y, b0.z, b0.w, b1.x, b1.y, b1.z, b1.w};
#pragma unroll
        for (int i = 0; i < 8; ++i)
#pragma unroll
            for (int j = 0; j < 8; ++j)
                acc[i][j] = fmaf(a[i], b[j], acc[i][j]);
    }
}

// ---------------------------------------------------------------------------
// K1: QKV projection with head-major scatter. sel: 0=Q 1=K 2=V
// grid (HD/TS=8, MM/TS=64), block 256
// ---------------------------------------------------------------------------
__global__ __launch_bounds__(256) void k_qkv(const float* __restrict__ x,
                                             const float* __restrict__ W,
                                             const float* __restrict__ bias,
                                             int sel) {
    __shared__ __align__(16) float SA[KS][SPAD];
    __shared__ __align__(16) float SB[KS][SPAD];
    int tid = threadIdx.x, tx = tid & 15, ty = tid >> 4;
    int e0 = blockIdx.x * TS;
    int m0 = blockIdx.y * TS;
    float acc[8][8] = {};

    for (int k0 = 0; k0 < DD; k0 += KS) {
        load_tileT(SA, x, DD, m0, k0, tid);
        load_tileT(SB, W, DD, e0, k0, tid);
        __syncthreads();
        mma_tile(SA, SB, ty, tx, acc);
        __syncthreads();
    }

    float* dst = (sel == 0) ? g_Q : (sel == 1) ? g_K : g_V;
    int h = e0 >> 7;  // whole tile within one head (TS==D)
#pragma unroll
    for (int i = 0; i < 8; ++i) {
        int m = m0 + ty * 8 + i;
        int b = m >> 9, l = m & 511;
        int base = (((h << 4) + b) * LL + l) * DD;
#pragma unroll
        for (int j = 0; j < 8; ++j) {
            int e = e0 + tx * 8 + j;
            int d = e & 127;
            dst[base + d] = acc[i][j] + bias[e];
        }
    }
}

// ---------------------------------------------------------------------------
// K2: scores S[n][q][k] = (mask ? -1e9 : Q.K) * inv_sqrt_d
// grid (LL/TS=4, LL/TS=4, HB=128), block 256
// ---------------------------------------------------------------------------
__global__ __launch_bounds__(256) void k_scores(const int* __restrict__ mask) {
    __shared__ __align__(16) float SA[KS][SPAD];
    __shared__ __align__(16) float SB[KS][SPAD];
    int tid = threadIdx.x, tx = tid & 15, ty = tid >> 4;
    int n = blockIdx.z;
    int kc0 = blockIdx.x * TS;
    int q0 = blockIdx.y * TS;
    const float* Qn = g_Q + n * (LL * DD);
    const float* Kn = g_K + n * (LL * DD);
    float acc[8][8] = {};

    for (int d0 = 0; d0 < DD; d0 += KS) {
        load_tileT(SA, Qn, DD, q0, d0, tid);
        load_tileT(SB, Kn, DD, kc0, d0, tid);
        __syncthreads();
        mma_tile(SA, SB, ty, tx, acc);
        __syncthreads();
    }

    const int* mrow = mask + (n & 15) * (LL * LL);
    float* Srow = g_S + n * (LL * LL);
#pragma unroll
    for (int i = 0; i < 8; ++i) {
        int q = q0 + ty * 8 + i;
#pragma unroll
        for (int j = 0; j < 8; ++j) {
            int kk = kc0 + tx * 8 + j;
            float v = mrow[q * LL + kk] ? -1e9f : acc[i][j];
            Srow[q * LL + kk] = v * INV_SQRT_D;
        }
    }
}

// ---------------------------------------------------------------------------
// K3: softmax over the QUERY axis (axis=1), in place on g_S.
// grid (LL/32=16, HB=128), block 256 = 32 k-lanes x 8 q-partitions
// ---------------------------------------------------------------------------
__global__ __launch_bounds__(256) void k_softmax() {
    int n = blockIdx.y;
    int k0 = blockIdx.x * 32;
    int tx = threadIdx.x & 31;
    int ty = threadIdx.x >> 5;
    float* base = g_S + n * (LL * LL) + k0 + tx;

    float m = -3.4e38f, z = 0.f;
    for (int q = ty; q < LL; q += 8) {
        float s = base[q * LL];
        float nm = fmaxf(m, s);
        z = z * __expf(m - nm) + __expf(s - nm);
        m = nm;
    }

    __shared__ float sm[8][32];
    __shared__ float sz[8][32];
    sm[ty][tx] = m;
    sz[ty][tx] = z;
    __syncthreads();

    float M = -3.4e38f;
#pragma unroll
    for (int i = 0; i < 8; ++i) M = fmaxf(M, sm[i][tx]);
    float Z = 0.f;
#pragma unroll
    for (int i = 0; i < 8; ++i) Z += sz[i][tx] * __expf(sm[i][tx] - M);
    float inv = 1.0f / Z;

    for (int q = ty; q < LL; q += 8) {
        float s = base[q * LL];
        base[q * LL] = __expf(s - M) * inv;
    }
}

// ---------------------------------------------------------------------------
// K4: att[n][q][d] = sum_k attn[n][q][k] * V[n][k][d]
// grid (1, LL/TS=4, HB=128), block 256
// ---------------------------------------------------------------------------
__global__ __launch_bounds__(256) void k_av() {
    __shared__ __align__(16) float SA[KS][SPAD];
    __shared__ __align__(16) float SB[KS][SPAD];
    int tid = threadIdx.x, tx = tid & 15, ty = tid >> 4;
    int n = blockIdx.z;
    int q0 = blockIdx.y * TS;
    const float* Pn = g_S + n * (LL * LL);
    const float* Vn = g_V + n * (LL * DD);
    float acc[8][8] = {};

    for (int k0 = 0; k0 < LL; k0 += KS) {
        load_tileT(SA, Pn, LL, q0, k0, tid);       // rows q, contraction k (last dim)
        load_tile_direct(SB, Vn, DD, k0, 0, tid);  // rows k (first dim), cols d
        __syncthreads();
        mma_tile(SA, SB, ty, tx, acc);
        __syncthreads();
    }

    float* dst = g_ATT + n * (LL * DD);
#pragma unroll
    for (int i = 0; i < 8; ++i) {
        int q = q0 + ty * 8 + i;
#pragma unroll
        for (int j = 0; j < 8; ++j) {
            int d = tx * 8 + j;
            dst[q * DD + d] = acc[i][j];
        }
    }
}

// ---------------------------------------------------------------------------
// K5: out[m][do] = sum_e ATTview[m][e] * W_o[do][e] + b_o[do]
// ATTview = g_ATT reinterpreted as [MM][HD] (the .view quirk, free)
// grid (1, MM/TS=64), block 256
// ---------------------------------------------------------------------------
__global__ __launch_bounds__(256) void k_out(const float* __restrict__ Wo,
                                             const float* __restrict__ bo,
                                             float* __restrict__ out) {
    __shared__ __align__(16) float SA[KS][SPAD];
    __shared__ __align__(16) float SB[KS][SPAD];
    int tid = threadIdx.x, tx = tid & 15, ty = tid >> 4;
    int m0 = blockIdx.y * TS;
    const float* A = g_ATT;  // [MM][HD] flat view
    float acc[8][8] = {};

    for (int k0 = 0; k0 < HD; k0 += KS) {
        load_tileT(SA, A, HD, m0, k0, tid);
        load_tileT(SB, Wo, HD, 0, k0, tid);   // Wo is [128][1024], full N tile
        __syncthreads();
        mma_tile(SA, SB, ty, tx, acc);
        __syncthreads();
    }

#pragma unroll
    for (int i = 0; i < 8; ++i) {
        int m = m0 + ty * 8 + i;
#pragma unroll
        for (int j = 0; j < 8; ++j) {
            int dout = tx * 8 + j;
            out[m * DD + dout] = acc[i][j] + bo[dout];
        }
    }
}

// ---------------------------------------------------------------------------
extern "C" void kernel_launch(void* const* d_in, const int* in_sizes, int n_in,
                              void* d_out, int out_size) {
    const float* x  = (const float*)d_in[0];
    const float* Wq = (const float*)d_in[1];
    const float* bq = (const float*)d_in[2];
    const float* Wk = (const float*)d_in[3];
    const float* bk = (const float*)d_in[4];
    const float* Wv = (const float*)d_in[5];
    const float* bv = (const float*)d_in[6];
    const float* Wo = (const float*)d_in[7];
    const float* bo = (const float*)d_in[8];
    const int*   mask = (const int*)d_in[9];
    float* out = (float*)d_out;

    k_qkv<<<dim3(HD / TS, MM / TS), 256>>>(x, Wq, bq, 0);
    k_qkv<<<dim3(HD / TS, MM / TS), 256>>>(x, Wk, bk, 1);
    k_qkv<<<dim3(HD / TS, MM / TS), 256>>>(x, Wv, bv, 2);
    k_scores<<<dim3(LL / TS, LL / TS, HB), 256>>>(mask);
    k_softmax<<<dim3(LL / 32, HB), 256>>>();
    k_av<<<dim3(1, LL / TS, HB), 256>>>();
    k_out<<<dim3(1, MM / TS), 256>>>(Wo, bo, out);
}

// round 5
// speedup vs baseline: 2.7517x; 2.7517x over previous
#include <cuda_runtime.h>
#include <cstdint>
#include <math.h>

// Problem constants
#define LL 512
#define DD 128
#define HB 128          // H*B
#define MM 8192         // B*L
#define HD 1024
#define INV_SQRT_D 0.08838834764831843f

// Scratch (device globals; allocation is forbidden)
__device__ __align__(128) float g_Q[HB * LL * DD];
__device__ __align__(128) float g_K[HB * LL * DD];
__device__ __align__(128) float g_Vt[HB * DD * LL];    // V transposed: [n][d][l]
__device__ __align__(128) float g_S[HB * LL * LL];
__device__ __align__(128) float g_ATT[HB * LL * DD];   // flat view == (B,L,H*D)

// ---------------------------------------------------------------------------
// Tiling: block 128x128, warps 4(m) x 2(n), warp tile 32x64, K chunk 32.
// Smem tile: [128 rows][36 floats] (32 K + 4 pad), both operands K-last.
// ---------------------------------------------------------------------------
#define KC 32
#define ROWPAD 36
#define TILE_B (128 * ROWPAD * 4)      // 18432 bytes per tile buffer
#define SMEM_BYTES (4 * TILE_B)        // A0,A1,B0,B1 = 73728

__device__ __forceinline__ uint32_t smem_u32(const void* p) {
    uint32_t a;
    asm("{ .reg .u64 t; cvta.to.shared.u64 t, %1; cvt.u32.u64 %0, t; }" : "=r"(a) : "l"(p));
    return a;
}
__device__ __forceinline__ void cp16(uint32_t saddr, const void* g) {
    asm volatile("cp.async.cg.shared.global [%0], [%1], 16;" :: "r"(saddr), "l"(g));
}
#define CP_COMMIT() asm volatile("cp.async.commit_group;" ::: "memory")
#define CP_WAIT(N)  asm volatile("cp.async.wait_group %0;" :: "n"(N) : "memory")

__device__ __forceinline__ uint32_t tf32_rna(float f) {
    uint32_t r;
    asm("cvt.rna.tf32.f32 %0, %1;" : "=r"(r) : "f"(f));
    return r;
}
// Split fp32 into hi (tf32) + lo (tf32 of residual). hi+lo ~= v to ~2^-24.
__device__ __forceinline__ void split_tf32(float v, uint32_t& hi, uint32_t& lo) {
    hi = tf32_rna(v);
    lo = tf32_rna(v - __uint_as_float(hi));
}

__device__ __forceinline__ void mma8(float acc[4],
                                     uint32_t a0, uint32_t a1, uint32_t a2, uint32_t a3,
                                     uint32_t b0, uint32_t b1) {
    asm volatile(
        "mma.sync.aligned.m16n8k8.row.col.f32.tf32.tf32.f32 "
        "{%0,%1,%2,%3}, {%4,%5,%6,%7}, {%8,%9}, {%0,%1,%2,%3};"
        : "+f"(acc[0]), "+f"(acc[1]), "+f"(acc[2]), "+f"(acc[3])
        : "r"(a0), "r"(a1), "r"(a2), "r"(a3), "r"(b0), "r"(b1));
}

// Issue async copy of a 128x32 f32 tile (row stride ld) into smem buffer.
__device__ __forceinline__ void load_async(uint32_t sbase, const float* __restrict__ src,
                                           int ld, int tid) {
#pragma unroll
    for (int i = 0; i < 4; ++i) {
        int idx = tid + i * 256;
        int row = idx >> 3;     // 0..127
        int c4 = idx & 7;       // 0..7 (float4 within the 32-wide K slab)
        cp16(sbase + (row * ROWPAD + c4 * 4) * 4, src + row * ld + c4 * 4);
    }
}

// One K=32 chunk of MMAs on the resident smem tiles — 3xTF32 split precision.
// acc += Ah*Bh + Ah*Bl + Al*Bh  (Al*Bl dropped, ~2^-24)
__device__ __forceinline__ void compute_chunk(const float (*As)[ROWPAD],
                                              const float (*Bs)[ROWPAD],
                                              int wm, int wn, int g, int t,
                                              float acc[2][8][4]) {
#pragma unroll
    for (int ks = 0; ks < 4; ++ks) {
        int k = ks * 8;
        uint32_t ah[2][4], al[2][4];
#pragma unroll
        for (int mt = 0; mt < 2; ++mt) {
            int r = wm * 32 + mt * 16;
            split_tf32(As[r + g][k + t],         ah[mt][0], al[mt][0]);
            split_tf32(As[r + g + 8][k + t],     ah[mt][1], al[mt][1]);
            split_tf32(As[r + g][k + t + 4],     ah[mt][2], al[mt][2]);
            split_tf32(As[r + g + 8][k + t + 4], ah[mt][3], al[mt][3]);
        }
#pragma unroll
        for (int nt = 0; nt < 8; ++nt) {
            int c = wn * 64 + nt * 8;
            uint32_t bh0, bl0, bh1, bl1;
            split_tf32(Bs[c + g][k + t],     bh0, bl0);
            split_tf32(Bs[c + g][k + t + 4], bh1, bl1);
#pragma unroll
            for (int mt = 0; mt < 2; ++mt) {
                mma8(acc[mt][nt], ah[mt][0], ah[mt][1], ah[mt][2], ah[mt][3], bh0, bh1);
                mma8(acc[mt][nt], ah[mt][0], ah[mt][1], ah[mt][2], ah[mt][3], bl0, bl1);
                mma8(acc[mt][nt], al[mt][0], al[mt][1], al[mt][2], al[mt][3], bh0, bh1);
            }
        }
    }
}

// Full main loop: nc K-chunks, 2-stage cp.async pipeline.
// A rows: block M tile (128 rows, stride lda). B rows: block N tile (128 rows, stride ldb).
__device__ __forceinline__ void gemm_main(char* sm, uint32_t smb,
                                          const float* __restrict__ A, int lda,
                                          const float* __restrict__ B, int ldb,
                                          int nc, int tid, int wm, int wn, int g, int t,
                                          float acc[2][8][4]) {
    load_async(smb, A, lda, tid);
    load_async(smb + 2 * TILE_B, B, ldb, tid);
    CP_COMMIT();
#pragma unroll 1
    for (int c = 0; c < nc; ++c) {
        if (c + 1 < nc) {
            int nb = (c + 1) & 1;
            load_async(smb + nb * TILE_B, A + (c + 1) * KC, lda, tid);
            load_async(smb + (2 + nb) * TILE_B, B + (c + 1) * KC, ldb, tid);
            CP_COMMIT();
            CP_WAIT(1);
        } else {
            CP_WAIT(0);
        }
        __syncthreads();
        int cb = c & 1;
        compute_chunk((const float(*)[ROWPAD])(sm + cb * TILE_B),
                      (const float(*)[ROWPAD])(sm + (2 + cb) * TILE_B),
                      wm, wn, g, t, acc);
        __syncthreads();
    }
}

// ---------------------------------------------------------------------------
// K1: QKV projection. grid (8, 64, 3), block 256.
// C[m][e] = sum_d x[m][d] * W[e][d]; +bias; head-major scatter.
// ---------------------------------------------------------------------------
__global__ __launch_bounds__(256) void k_qkv(
    const float* __restrict__ x,
    const float* __restrict__ Wq, const float* __restrict__ bq,
    const float* __restrict__ Wk, const float* __restrict__ bk,
    const float* __restrict__ Wv, const float* __restrict__ bv) {
    extern __shared__ char sm[];
    uint32_t smb = smem_u32(sm);
    int tid = threadIdx.x, wid = tid >> 5, lane = tid & 31;
    int wm = wid & 3, wn = wid >> 2, g = lane >> 2, t = lane & 3;
    int sel = blockIdx.z;
    int e0 = blockIdx.x * 128;   // one full head (D=128)
    int m0 = blockIdx.y * 128;
    const float* W = (sel == 0) ? Wq : (sel == 1) ? Wk : Wv;
    const float* bias = (sel == 0) ? bq : (sel == 1) ? bk : bv;

    float acc[2][8][4] = {};
    gemm_main(sm, smb, x + m0 * DD, DD, W + e0 * DD, DD, 4, tid, wm, wn, g, t, acc);

    int h = e0 >> 7;
#pragma unroll
    for (int mt = 0; mt < 2; ++mt) {
#pragma unroll
        for (int nt = 0; nt < 8; ++nt) {
            int col = wn * 64 + nt * 8 + t * 2;   // d within head
            float bi0 = bias[e0 + col], bi1 = bias[e0 + col + 1];
#pragma unroll
            for (int half = 0; half < 2; ++half) {
                int row = wm * 32 + mt * 16 + g + half * 8;
                int m = m0 + row;
                int b = m >> 9, l = m & 511;
                int n = (h << 4) + b;
                float v0 = acc[mt][nt][half * 2] + bi0;
                float v1 = acc[mt][nt][half * 2 + 1] + bi1;
                if (sel < 2) {
                    float* dst = ((sel == 0) ? g_Q : g_K) + (n * LL + l) * DD + col;
                    *(float2*)dst = make_float2(v0, v1);
                } else {
                    float* dst = g_Vt + n * (DD * LL) + l;
                    dst[col * LL] = v0;
                    dst[(col + 1) * LL] = v1;
                }
            }
        }
    }
}

// ---------------------------------------------------------------------------
// K2: scores. grid (4, 4, 128), block 256.
// S[n][q][k] = (mask ? -1e9 : Q.K) * inv_sqrt_d
// ---------------------------------------------------------------------------
__global__ __launch_bounds__(256) void k_scores(const int* __restrict__ mask) {
    extern __shared__ char sm[];
    uint32_t smb = smem_u32(sm);
    int tid = threadIdx.x, wid = tid >> 5, lane = tid & 31;
    int wm = wid & 3, wn = wid >> 2, g = lane >> 2, t = lane & 3;
    int n = blockIdx.z;
    int kc0 = blockIdx.x * 128;
    int q0 = blockIdx.y * 128;

    float acc[2][8][4] = {};
    gemm_main(sm, smb, g_Q + (n * LL + q0) * DD, DD,
              g_K + (n * LL + kc0) * DD, DD, 4, tid, wm, wn, g, t, acc);

    const int* mbase = mask + (n & 15) * (LL * LL);
    float* sbase = g_S + n * (LL * LL);
#pragma unroll
    for (int mt = 0; mt < 2; ++mt) {
#pragma unroll
        for (int nt = 0; nt < 8; ++nt) {
            int col = kc0 + wn * 64 + nt * 8 + t * 2;
#pragma unroll
            for (int half = 0; half < 2; ++half) {
                int q = q0 + wm * 32 + mt * 16 + g + half * 8;
                int2 mk = *(const int2*)(mbase + q * LL + col);
                float v0 = (mk.x ? -1e9f : acc[mt][nt][half * 2]) * INV_SQRT_D;
                float v1 = (mk.y ? -1e9f : acc[mt][nt][half * 2 + 1]) * INV_SQRT_D;
                *(float2*)(sbase + q * LL + col) = make_float2(v0, v1);
            }
        }
    }
}

// ---------------------------------------------------------------------------
// K3: softmax over the QUERY axis (axis=1), in place on g_S.
// grid (16, 128), block 256 = 32 k-lanes x 8 q-partitions
// ---------------------------------------------------------------------------
__global__ __launch_bounds__(256) void k_softmax() {
    int n = blockIdx.y;
    int k0 = blockIdx.x * 32;
    int tx = threadIdx.x & 31;
    int ty = threadIdx.x >> 5;
    float* base = g_S + n * (LL * LL) + k0 + tx;

    float m = -3.4e38f, z = 0.f;
    for (int q = ty; q < LL; q += 8) {
        float s = base[q * LL];
        float nm = fmaxf(m, s);
        z = z * __expf(m - nm) + __expf(s - nm);
        m = nm;
    }
    __shared__ float smx[8][32];
    __shared__ float szx[8][32];
    smx[ty][tx] = m;
    szx[ty][tx] = z;
    __syncthreads();
    float M = -3.4e38f;
#pragma unroll
    for (int i = 0; i < 8; ++i) M = fmaxf(M, smx[i][tx]);
    float Z = 0.f;
#pragma unroll
    for (int i = 0; i < 8; ++i) Z += szx[i][tx] * __expf(smx[i][tx] - M);
    float inv = 1.0f / Z;
    for (int q = ty; q < LL; q += 8) {
        float s = base[q * LL];
        base[q * LL] = __expf(s - M) * inv;
    }
}

// ---------------------------------------------------------------------------
// K4: AV. grid (1, 4, 128), block 256.
// ATT[n][q][d] = sum_k P[n][q][k] * Vt[n][d][k]    (K = 512 -> 16 chunks)
// ---------------------------------------------------------------------------
__global__ __launch_bounds__(256) void k_av() {
    extern __shared__ char sm[];
    uint32_t smb = smem_u32(sm);
    int tid = threadIdx.x, wid = tid >> 5, lane = tid & 31;
    int wm = wid & 3, wn = wid >> 2, g = lane >> 2, t = lane & 3;
    int n = blockIdx.z;
    int q0 = blockIdx.y * 128;

    float acc[2][8][4] = {};
    gemm_main(sm, smb, g_S + (n * LL + q0) * LL, LL,
              g_Vt + n * (DD * LL), LL, 16, tid, wm, wn, g, t, acc);

    float* abase = g_ATT + n * (LL * DD);
#pragma unroll
    for (int mt = 0; mt < 2; ++mt) {
#pragma unroll
        for (int nt = 0; nt < 8; ++nt) {
            int col = wn * 64 + nt * 8 + t * 2;
#pragma unroll
            for (int half = 0; half < 2; ++half) {
                int q = q0 + wm * 32 + mt * 16 + g + half * 8;
                *(float2*)(abase + q * DD + col) =
                    make_float2(acc[mt][nt][half * 2], acc[mt][nt][half * 2 + 1]);
            }
        }
    }
}

// ---------------------------------------------------------------------------
// K5: output projection. grid (1, 64), block 256.
// out[m][o] = sum_e ATTflat[m][e] * Wo[o][e] + bo[o]   (K = 1024 -> 32 chunks)
// ---------------------------------------------------------------------------
__global__ __launch_bounds__(256) void k_out(const float* __restrict__ Wo,
                                             const float* __restrict__ bo,
                                             float* __restrict__ out) {
    extern __shared__ char sm[];
    uint32_t smb = smem_u32(sm);
    int tid = threadIdx.x, wid = tid >> 5, lane = tid & 31;
    int wm = wid & 3, wn = wid >> 2, g = lane >> 2, t = lane & 3;
    int m0 = blockIdx.y * 128;

    float acc[2][8][4] = {};
    gemm_main(sm, smb, g_ATT + m0 * HD, HD, Wo, HD, 32, tid, wm, wn, g, t, acc);

#pragma unroll
    for (int mt = 0; mt < 2; ++mt) {
#pragma unroll
        for (int nt = 0; nt < 8; ++nt) {
            int col = wn * 64 + nt * 8 + t * 2;
            float b0 = bo[col], b1 = bo[col + 1];
#pragma unroll
            for (int half = 0; half < 2; ++half) {
                int m = m0 + wm * 32 + mt * 16 + g + half * 8;
                *(float2*)(out + m * DD + col) =
                    make_float2(acc[mt][nt][half * 2] + b0,
                                acc[mt][nt][half * 2 + 1] + b1);
            }
        }
    }
}

// ---------------------------------------------------------------------------
extern "C" void kernel_launch(void* const* d_in, const int* in_sizes, int n_in,
                              void* d_out, int out_size) {
    const float* x  = (const float*)d_in[0];
    const float* Wq = (const float*)d_in[1];
    const float* bq = (const float*)d_in[2];
    const float* Wk = (const float*)d_in[3];
    const float* bk = (const float*)d_in[4];
    const float* Wv = (const float*)d_in[5];
    const float* bv = (const float*)d_in[6];
    const float* Wo = (const float*)d_in[7];
    const float* bo = (const float*)d_in[8];
    const int*   mask = (const int*)d_in[9];
    float* out = (float*)d_out;

    cudaFuncSetAttribute(k_qkv,    cudaFuncAttributeMaxDynamicSharedMemorySize, SMEM_BYTES);
    cudaFuncSetAttribute(k_scores, cudaFuncAttributeMaxDynamicSharedMemorySize, SMEM_BYTES);
    cudaFuncSetAttribute(k_av,     cudaFuncAttributeMaxDynamicSharedMemorySize, SMEM_BYTES);
    cudaFuncSetAttribute(k_out,    cudaFuncAttributeMaxDynamicSharedMemorySize, SMEM_BYTES);

    k_qkv<<<dim3(8, 64, 3), 256, SMEM_BYTES>>>(x, Wq, bq, Wk, bk, Wv, bv);
    k_scores<<<dim3(4, 4, 128), 256, SMEM_BYTES>>>(mask);
    k_softmax<<<dim3(16, 128), 256>>>();
    k_av<<<dim3(1, 4, 128), 256, SMEM_BYTES>>>();
    k_out<<<dim3(1, 64), 256, SMEM_BYTES>>>(Wo, bo, out);
}

// round 6
// speedup vs baseline: 2.8004x; 1.0177x over previous
#include <cuda_runtime.h>
#include <cstdint>
#include <math.h>

// Problem constants
#define LL 512
#define DD 128
#define HB 128          // H*B
#define MM 8192         // B*L
#define HD 1024
#define INV_SQRT_D 0.08838834764831843f

// Scratch (device globals; allocation is forbidden)
__device__ __align__(128) float g_Q[HB * LL * DD];
__device__ __align__(128) float g_K[HB * LL * DD];
__device__ __align__(128) float g_Vt[HB * DD * LL];    // V transposed: [n][d][l]
__device__ __align__(128) float g_S[HB * LL * LL];     // raw masked+scaled scores
__device__ __align__(128) float g_ATT[HB * LL * DD];   // flat view == (B,L,H*D)
// Query-axis softmax stats: partial per 128-q block, then combined
__device__ __align__(128) float g_pmax[4 * HB * LL];
__device__ __align__(128) float g_psum[4 * HB * LL];
__device__ __align__(128) float g_M[HB * LL];
__device__ __align__(128) float g_inv[HB * LL];

// ---------------------------------------------------------------------------
// Tiling: block 128x128, warps 4(m) x 2(n), warp tile 32x64, K chunk 32.
// ---------------------------------------------------------------------------
#define KC 32
#define ROWPAD 36
#define TILE_B (128 * ROWPAD * 4)      // 18432 bytes per tile buffer
#define SMEM_BYTES (4 * TILE_B)        // A0,A1,B0,B1 = 73728

__device__ __forceinline__ uint32_t smem_u32(const void* p) {
    uint32_t a;
    asm("{ .reg .u64 t; cvta.to.shared.u64 t, %1; cvt.u32.u64 %0, t; }" : "=r"(a) : "l"(p));
    return a;
}
__device__ __forceinline__ void cp16(uint32_t saddr, const void* g) {
    asm volatile("cp.async.cg.shared.global [%0], [%1], 16;" :: "r"(saddr), "l"(g));
}
#define CP_COMMIT() asm volatile("cp.async.commit_group;" ::: "memory")
#define CP_WAIT(N)  asm volatile("cp.async.wait_group %0;" :: "n"(N) : "memory")

__device__ __forceinline__ uint32_t tf32_rna(float f) {
    uint32_t r;
    asm("cvt.rna.tf32.f32 %0, %1;" : "=r"(r) : "f"(f));
    return r;
}
__device__ __forceinline__ void split_tf32(float v, uint32_t& hi, uint32_t& lo) {
    hi = tf32_rna(v);
    lo = tf32_rna(v - __uint_as_float(hi));
}

__device__ __forceinline__ void mma8(float acc[4],
                                     uint32_t a0, uint32_t a1, uint32_t a2, uint32_t a3,
                                     uint32_t b0, uint32_t b1) {
    asm volatile(
        "mma.sync.aligned.m16n8k8.row.col.f32.tf32.tf32.f32 "
        "{%0,%1,%2,%3}, {%4,%5,%6,%7}, {%8,%9}, {%0,%1,%2,%3};"
        : "+f"(acc[0]), "+f"(acc[1]), "+f"(acc[2]), "+f"(acc[3])
        : "r"(a0), "r"(a1), "r"(a2), "r"(a3), "r"(b0), "r"(b1));
}

__device__ __forceinline__ void load_async(uint32_t sbase, const float* __restrict__ src,
                                           int ld, int tid) {
#pragma unroll
    for (int i = 0; i < 4; ++i) {
        int idx = tid + i * 256;
        int row = idx >> 3;
        int c4 = idx & 7;
        cp16(sbase + (row * ROWPAD + c4 * 4) * 4, src + row * ld + c4 * 4);
    }
}

// One K=32 chunk — 3xTF32 split, term-major in nt-pairs (MMA dep distance 4).
// EXP: A element -> exp(a - M[k]) * inv[k] before split (fused softmax apply).
template<bool EXP>
__device__ __forceinline__ void compute_chunk(const float (*As)[ROWPAD],
                                              const float (*Bs)[ROWPAD],
                                              int wm, int wn, int g, int t,
                                              const float* __restrict__ Mrow,
                                              const float* __restrict__ Irow,
                                              float acc[2][8][4]) {
#pragma unroll
    for (int ks = 0; ks < 4; ++ks) {
        int k = ks * 8;
        float M0 = 0.f, I0 = 0.f, M1 = 0.f, I1 = 0.f;
        if (EXP) {
            M0 = Mrow[k + t];     I0 = Irow[k + t];
            M1 = Mrow[k + t + 4]; I1 = Irow[k + t + 4];
        }
        uint32_t ah[2][4], al[2][4];
#pragma unroll
        for (int mt = 0; mt < 2; ++mt) {
            int r = wm * 32 + mt * 16;
            float a0 = As[r + g][k + t];
            float a1 = As[r + g + 8][k + t];
            float a2 = As[r + g][k + t + 4];
            float a3 = As[r + g + 8][k + t + 4];
            if (EXP) {
                a0 = __expf(a0 - M0) * I0;
                a1 = __expf(a1 - M0) * I0;
                a2 = __expf(a2 - M1) * I1;
                a3 = __expf(a3 - M1) * I1;
            }
            split_tf32(a0, ah[mt][0], al[mt][0]);
            split_tf32(a1, ah[mt][1], al[mt][1]);
            split_tf32(a2, ah[mt][2], al[mt][2]);
            split_tf32(a3, ah[mt][3], al[mt][3]);
        }
#pragma unroll
        for (int np = 0; np < 4; ++np) {
            int nt0 = np * 2, nt1 = nt0 + 1;
            int c0 = wn * 64 + nt0 * 8;
            int c1 = wn * 64 + nt1 * 8;
            uint32_t bh00, bl00, bh01, bl01, bh10, bl10, bh11, bl11;
            split_tf32(Bs[c0 + g][k + t],     bh00, bl00);
            split_tf32(Bs[c0 + g][k + t + 4], bh01, bl01);
            split_tf32(Bs[c1 + g][k + t],     bh10, bl10);
            split_tf32(Bs[c1 + g][k + t + 4], bh11, bl11);
            // hh terms (4 independent)
            mma8(acc[0][nt0], ah[0][0], ah[0][1], ah[0][2], ah[0][3], bh00, bh01);
            mma8(acc[1][nt0], ah[1][0], ah[1][1], ah[1][2], ah[1][3], bh00, bh01);
            mma8(acc[0][nt1], ah[0][0], ah[0][1], ah[0][2], ah[0][3], bh10, bh11);
            mma8(acc[1][nt1], ah[1][0], ah[1][1], ah[1][2], ah[1][3], bh10, bh11);
            // hl terms
            mma8(acc[0][nt0], ah[0][0], ah[0][1], ah[0][2], ah[0][3], bl00, bl01);
            mma8(acc[1][nt0], ah[1][0], ah[1][1], ah[1][2], ah[1][3], bl00, bl01);
            mma8(acc[0][nt1], ah[0][0], ah[0][1], ah[0][2], ah[0][3], bl10, bl11);
            mma8(acc[1][nt1], ah[1][0], ah[1][1], ah[1][2], ah[1][3], bl10, bl11);
            // lh terms
            mma8(acc[0][nt0], al[0][0], al[0][1], al[0][2], al[0][3], bh00, bh01);
            mma8(acc[1][nt0], al[1][0], al[1][1], al[1][2], al[1][3], bh00, bh01);
            mma8(acc[0][nt1], al[0][0], al[0][1], al[0][2], al[0][3], bh10, bh11);
            mma8(acc[1][nt1], al[1][0], al[1][1], al[1][2], al[1][3], bh10, bh11);
        }
    }
}

template<bool EXP>
__device__ __forceinline__ void gemm_main(char* sm, uint32_t smb,
                                          const float* __restrict__ A, int lda,
                                          const float* __restrict__ B, int ldb,
                                          int nc, int tid, int wm, int wn, int g, int t,
                                          const float* __restrict__ Mb,
                                          const float* __restrict__ Ib,
                                          float acc[2][8][4]) {
    load_async(smb, A, lda, tid);
    load_async(smb + 2 * TILE_B, B, ldb, tid);
    CP_COMMIT();
#pragma unroll 1
    for (int c = 0; c < nc; ++c) {
        if (c + 1 < nc) {
            int nb = (c + 1) & 1;
            load_async(smb + nb * TILE_B, A + (c + 1) * KC, lda, tid);
            load_async(smb + (2 + nb) * TILE_B, B + (c + 1) * KC, ldb, tid);
            CP_COMMIT();
            CP_WAIT(1);
        } else {
            CP_WAIT(0);
        }
        __syncthreads();
        int cb = c & 1;
        compute_chunk<EXP>((const float(*)[ROWPAD])(sm + cb * TILE_B),
                           (const float(*)[ROWPAD])(sm + (2 + cb) * TILE_B),
                           wm, wn, g, t,
                           EXP ? Mb + c * KC : (const float*)nullptr,
                           EXP ? Ib + c * KC : (const float*)nullptr,
                           acc);
        __syncthreads();
    }
}

// ---------------------------------------------------------------------------
// K1: QKV projection. grid (8, 64, 3), block 256.
// ---------------------------------------------------------------------------
__global__ __launch_bounds__(256, 2) void k_qkv(
    const float* __restrict__ x,
    const float* __restrict__ Wq, const float* __restrict__ bq,
    const float* __restrict__ Wk, const float* __restrict__ bk,
    const float* __restrict__ Wv, const float* __restrict__ bv) {
    extern __shared__ char sm[];
    uint32_t smb = smem_u32(sm);
    int tid = threadIdx.x, wid = tid >> 5, lane = tid & 31;
    int wm = wid & 3, wn = wid >> 2, g = lane >> 2, t = lane & 3;
    int sel = blockIdx.z;
    int e0 = blockIdx.x * 128;
    int m0 = blockIdx.y * 128;
    const float* W = (sel == 0) ? Wq : (sel == 1) ? Wk : Wv;
    const float* bias = (sel == 0) ? bq : (sel == 1) ? bk : bv;

    float acc[2][8][4] = {};
    gemm_main<false>(sm, smb, x + m0 * DD, DD, W + e0 * DD, DD, 4,
                     tid, wm, wn, g, t, nullptr, nullptr, acc);

    int h = e0 >> 7;
#pragma unroll
    for (int mt = 0; mt < 2; ++mt) {
#pragma unroll
        for (int nt = 0; nt < 8; ++nt) {
            int col = wn * 64 + nt * 8 + t * 2;
            float bi0 = bias[e0 + col], bi1 = bias[e0 + col + 1];
#pragma unroll
            for (int half = 0; half < 2; ++half) {
                int row = wm * 32 + mt * 16 + g + half * 8;
                int m = m0 + row;
                int b = m >> 9, l = m & 511;
                int n = (h << 4) + b;
                float v0 = acc[mt][nt][half * 2] + bi0;
                float v1 = acc[mt][nt][half * 2 + 1] + bi1;
                if (sel < 2) {
                    float* dst = ((sel == 0) ? g_Q : g_K) + (n * LL + l) * DD + col;
                    *(float2*)dst = make_float2(v0, v1);
                } else {
                    float* dst = g_Vt + n * (DD * LL) + l;
                    dst[col * LL] = v0;
                    dst[(col + 1) * LL] = v1;
                }
            }
        }
    }
}

// ---------------------------------------------------------------------------
// K2: scores + per-block column softmax partials. grid (4, 4, 128), block 256.
// ---------------------------------------------------------------------------
__global__ __launch_bounds__(256, 2) void k_scores(const int* __restrict__ mask) {
    extern __shared__ char sm[];
    uint32_t smb = smem_u32(sm);
    int tid = threadIdx.x, wid = tid >> 5, lane = tid & 31;
    int wm = wid & 3, wn = wid >> 2, g = lane >> 2, t = lane & 3;
    int n = blockIdx.z;
    int kc0 = blockIdx.x * 128;
    int q0 = blockIdx.y * 128;

    float acc[2][8][4] = {};
    gemm_main<false>(sm, smb, g_Q + (n * LL + q0) * DD, DD,
                     g_K + (n * LL + kc0) * DD, DD, 4,
                     tid, wm, wn, g, t, nullptr, nullptr, acc);

    // Mask + scale into acc; store raw S.
    const int* mbase = mask + (n & 15) * (LL * LL);
    float* sbase = g_S + n * (LL * LL);
#pragma unroll
    for (int mt = 0; mt < 2; ++mt) {
#pragma unroll
        for (int nt = 0; nt < 8; ++nt) {
            int col = kc0 + wn * 64 + nt * 8 + t * 2;
#pragma unroll
            for (int half = 0; half < 2; ++half) {
                int q = q0 + wm * 32 + mt * 16 + g + half * 8;
                int2 mk = *(const int2*)(mbase + q * LL + col);
                float v0 = (mk.x ? -1e9f : acc[mt][nt][half * 2]) * INV_SQRT_D;
                float v1 = (mk.y ? -1e9f : acc[mt][nt][half * 2 + 1]) * INV_SQRT_D;
                *(float2*)(sbase + q * LL + col) = make_float2(v0, v1);
                acc[mt][nt][half * 2] = v0;
                acc[mt][nt][half * 2 + 1] = v1;
            }
        }
    }

    // Column stats over this block's 128 q rows (softmax is over the q axis).
    float* smax = (float*)sm;          // [4 wm][128 col]
    float* ssum = ((float*)sm) + 512;  // [4 wm][128 col]

    // Phase A: per-column max (in-thread 4 -> butterfly over g -> smem over wm)
#pragma unroll
    for (int nt = 0; nt < 8; ++nt)
#pragma unroll
        for (int e = 0; e < 2; ++e) {
            float m = fmaxf(fmaxf(acc[0][nt][e], acc[0][nt][2 + e]),
                            fmaxf(acc[1][nt][e], acc[1][nt][2 + e]));
            m = fmaxf(m, __shfl_xor_sync(0xffffffffu, m, 16));
            m = fmaxf(m, __shfl_xor_sync(0xffffffffu, m, 8));
            m = fmaxf(m, __shfl_xor_sync(0xffffffffu, m, 4));
            if (g == 0) smax[wm * 128 + wn * 64 + nt * 8 + t * 2 + e] = m;
        }
    __syncthreads();
    float Mcol[8][2];
#pragma unroll
    for (int nt = 0; nt < 8; ++nt)
#pragma unroll
        for (int e = 0; e < 2; ++e) {
            int col = wn * 64 + nt * 8 + t * 2 + e;
            Mcol[nt][e] = fmaxf(fmaxf(smax[col], smax[128 + col]),
                                fmaxf(smax[256 + col], smax[384 + col]));
        }
    // Phase B: per-column sum of exp(v - M)
#pragma unroll
    for (int nt = 0; nt < 8; ++nt)
#pragma unroll
        for (int e = 0; e < 2; ++e) {
            float Mv = Mcol[nt][e];
            float z = __expf(acc[0][nt][e] - Mv) + __expf(acc[0][nt][2 + e] - Mv)
                    + __expf(acc[1][nt][e] - Mv) + __expf(acc[1][nt][2 + e] - Mv);
            z += __shfl_xor_sync(0xffffffffu, z, 16);
            z += __shfl_xor_sync(0xffffffffu, z, 8);
            z += __shfl_xor_sync(0xffffffffu, z, 4);
            if (g == 0) ssum[wm * 128 + wn * 64 + nt * 8 + t * 2 + e] = z;
        }
    __syncthreads();
    // One thread per column writes the block partial.
    if (wm == 0 && g == 0) {
#pragma unroll
        for (int nt = 0; nt < 8; ++nt)
#pragma unroll
            for (int e = 0; e < 2; ++e) {
                int col = wn * 64 + nt * 8 + t * 2 + e;
                float z = ssum[col] + ssum[128 + col] + ssum[256 + col] + ssum[384 + col];
                int gidx = ((blockIdx.y * HB + n) * LL) + kc0 + col;
                g_pmax[gidx] = Mcol[nt][e];
                g_psum[gidx] = z;
            }
    }
}

// ---------------------------------------------------------------------------
// K3: combine 4 q-block partials -> column M and 1/Z. grid 256, block 256.
// ---------------------------------------------------------------------------
__global__ __launch_bounds__(256) void k_colstats() {
    int idx = blockIdx.x * 256 + threadIdx.x;   // (n<<9)|k, 65536 total
    float m0 = g_pmax[idx];
    float m1 = g_pmax[65536 + idx];
    float m2 = g_pmax[131072 + idx];
    float m3 = g_pmax[196608 + idx];
    float M = fmaxf(fmaxf(m0, m1), fmaxf(m2, m3));
    float Z = g_psum[idx] * __expf(m0 - M)
            + g_psum[65536 + idx] * __expf(m1 - M)
            + g_psum[131072 + idx] * __expf(m2 - M)
            + g_psum[196608 + idx] * __expf(m3 - M);
    g_M[idx] = M;
    g_inv[idx] = 1.0f / Z;
}

// ---------------------------------------------------------------------------
// K4: AV with fused softmax apply on A. grid (1, 4, 128), block 256.
// ATT[n][q][d] = sum_k exp(S[n][q][k]-M[n][k])*inv[n][k] * Vt[n][d][k]
// ---------------------------------------------------------------------------
__global__ __launch_bounds__(256, 2) void k_av() {
    extern __shared__ char sm[];
    uint32_t smb = smem_u32(sm);
    int tid = threadIdx.x, wid = tid >> 5, lane = tid & 31;
    int wm = wid & 3, wn = wid >> 2, g = lane >> 2, t = lane & 3;
    int n = blockIdx.z;
    int q0 = blockIdx.y * 128;

    float acc[2][8][4] = {};
    gemm_main<true>(sm, smb, g_S + (n * LL + q0) * LL, LL,
                    g_Vt + n * (DD * LL), LL, 16,
                    tid, wm, wn, g, t, g_M + n * LL, g_inv + n * LL, acc);

    float* abase = g_ATT + n * (LL * DD);
#pragma unroll
    for (int mt = 0; mt < 2; ++mt) {
#pragma unroll
        for (int nt = 0; nt < 8; ++nt) {
            int col = wn * 64 + nt * 8 + t * 2;
#pragma unroll
            for (int half = 0; half < 2; ++half) {
                int q = q0 + wm * 32 + mt * 16 + g + half * 8;
                *(float2*)(abase + q * DD + col) =
                    make_float2(acc[mt][nt][half * 2], acc[mt][nt][half * 2 + 1]);
            }
        }
    }
}

// ---------------------------------------------------------------------------
// K5: output projection. grid (1, 64), block 256.
// ---------------------------------------------------------------------------
__global__ __launch_bounds__(256, 2) void k_out(const float* __restrict__ Wo,
                                                const float* __restrict__ bo,
                                                float* __restrict__ out) {
    extern __shared__ char sm[];
    uint32_t smb = smem_u32(sm);
    int tid = threadIdx.x, wid = tid >> 5, lane = tid & 31;
    int wm = wid & 3, wn = wid >> 2, g = lane >> 2, t = lane & 3;
    int m0 = blockIdx.y * 128;

    float acc[2][8][4] = {};
    gemm_main<false>(sm, smb, g_ATT + m0 * HD, HD, Wo, HD, 32,
                     tid, wm, wn, g, t, nullptr, nullptr, acc);

#pragma unroll
    for (int mt = 0; mt < 2; ++mt) {
#pragma unroll
        for (int nt = 0; nt < 8; ++nt) {
            int col = wn * 64 + nt * 8 + t * 2;
            float b0 = bo[col], b1 = bo[col + 1];
#pragma unroll
            for (int half = 0; half < 2; ++half) {
                int m = m0 + wm * 32 + mt * 16 + g + half * 8;
                *(float2*)(out + m * DD + col) =
                    make_float2(acc[mt][nt][half * 2] + b0,
                                acc[mt][nt][half * 2 + 1] + b1);
            }
        }
    }
}

// ---------------------------------------------------------------------------
extern "C" void kernel_launch(void* const* d_in, const int* in_sizes, int n_in,
                              void* d_out, int out_size) {
    const float* x  = (const float*)d_in[0];
    const float* Wq = (const float*)d_in[1];
    const float* bq = (const float*)d_in[2];
    const float* Wk = (const float*)d_in[3];
    const float* bk = (const float*)d_in[4];
    const float* Wv = (const float*)d_in[5];
    const float* bv = (const float*)d_in[6];
    const float* Wo = (const float*)d_in[7];
    const float* bo = (const float*)d_in[8];
    const int*   mask = (const int*)d_in[9];
    float* out = (float*)d_out;

    cudaFuncSetAttribute(k_qkv,    cudaFuncAttributeMaxDynamicSharedMemorySize, SMEM_BYTES);
    cudaFuncSetAttribute(k_scores, cudaFuncAttributeMaxDynamicSharedMemorySize, SMEM_BYTES);
    cudaFuncSetAttribute(k_av,     cudaFuncAttributeMaxDynamicSharedMemorySize, SMEM_BYTES);
    cudaFuncSetAttribute(k_out,    cudaFuncAttributeMaxDynamicSharedMemorySize, SMEM_BYTES);

    k_qkv<<<dim3(8, 64, 3), 256, SMEM_BYTES>>>(x, Wq, bq, Wk, bk, Wv, bv);
    k_scores<<<dim3(4, 4, 128), 256, SMEM_BYTES>>>(mask);
    k_colstats<<<256, 256>>>();
    k_av<<<dim3(1, 4, 128), 256, SMEM_BYTES>>>();
    k_out<<<dim3(1, 64), 256, SMEM_BYTES>>>(Wo, bo, out);
}